// round 11
// baseline (speedup 1.0000x reference)
#include <cuda_runtime.h>
#include <cuda_bf16.h>
#include <cstdint>

#define D_     512
#define NH_    8
#define HD_    64
#define NL_    6
#define DFF_   2048
#define VOCAB  1027
#define PAD_ID 1026
#define B_     256
#define SENC_  16
#define L_     61
#define NTOK   (B_ * L_)   // 15616 = 122 * 128

// ---------------- device scratch ----------------
__device__ float    g_x[NTOK * D_];            // residual stream (fp32)
__device__ float    g_t[NTOK * D_];            // gemm fp32 output scratch
__device__ float    g_qkv[NTOK * 3 * D_];      // qkv (fp32)
__device__ uint32_t g_h[(size_t)NTOK * DFF_];  // ff1 out (permuted tf32)
__device__ float    g_yca[B_ * D_];
__device__ float    g_padmask[NTOK];
__device__ uint32_t g_xp[NTOK * D_];           // x as permuted tf32
__device__ uint32_t g_ap[NTOK * D_];           // attn out as permuted tf32
__device__ uint32_t g_ep[B_ * D_];             // encoder mem token, permuted tf32
__device__ uint32_t g_vmemp[B_ * D_];          // ca1 out, permuted tf32
// converted weights (permuted tf32)
__device__ uint32_t g_w_sain[NL_ * 3 * D_ * D_];
__device__ uint32_t g_w_saout[NL_ * D_ * D_];
__device__ uint32_t g_w_cain[NL_ * 3 * D_ * D_];
__device__ uint32_t g_w_caout[NL_ * D_ * D_];
__device__ uint32_t g_w_ff1[NL_ * DFF_ * D_];
__device__ uint32_t g_w_ff2[NL_ * D_ * DFF_];
__device__ uint32_t g_w_out[VOCAB * D_];

// ---------------- helpers ----------------
__device__ __forceinline__ uint32_t smem_u32(const void* p) {
    uint32_t a;
    asm("{ .reg .u64 t; cvta.to.shared.u64 t, %1; cvt.u32.u64 %0, t; }" : "=r"(a) : "l"(p));
    return a;
}
__device__ __forceinline__ uint32_t f2tf32(float f) {
    uint32_t u; asm("cvt.rna.tf32.f32 %0, %1;" : "=r"(u) : "f"(f)); return u;
}
// permuted position within each 32-wide k block: p = (k&3)*8 + (k&31)/4
__device__ __forceinline__ int pp(int k) {
    return (k & ~31) | (((k & 3) << 3) | ((k & 31) >> 2));
}
__device__ __forceinline__ void mma_tf32(float* c, const uint32_t* a, const uint32_t* b) {
    asm volatile(
        "mma.sync.aligned.m16n8k8.row.col.f32.tf32.tf32.f32 "
        "{%0,%1,%2,%3}, {%4,%5,%6,%7}, {%8,%9}, {%0,%1,%2,%3};"
        : "+f"(c[0]), "+f"(c[1]), "+f"(c[2]), "+f"(c[3])
        : "r"(a[0]), "r"(a[1]), "r"(a[2]), "r"(a[3]), "r"(b[0]), "r"(b[1]));
}
__device__ __forceinline__ void cp16(uint32_t dst, const void* src, bool ok) {
    int sz = ok ? 16 : 0;
    asm volatile("cp.async.ca.shared.global [%0], [%1], 16, %2;"
                 :: "r"(dst), "l"(src), "r"(sz));
}
#define CP_COMMIT() asm volatile("cp.async.commit_group;" ::: "memory")

// smem geometry (u32): row stride 36, 128 rows A + 128 rows B per stage, 3 stages
#define RS      36
#define ABUF_U  (128 * RS)          // 4608
#define STG_U   (2 * ABUF_U)        // 9216
#define SM_BYTES (3 * STG_U * 4)    // 110592

// ---------------- weight conversion: fp32 -> permuted tf32 ----------------
__global__ void conv_perm(const float* __restrict__ src, uint32_t* __restrict__ dst, int total) {
    int i = (blockIdx.x * blockDim.x + threadIdx.x) * 4;
    if (i >= total) return;
    float4 v = *(const float4*)(src + i);
    dst[pp(i + 0)] = f2tf32(v.x);
    dst[pp(i + 1)] = f2tf32(v.y);
    dst[pp(i + 2)] = f2tf32(v.z);
    dst[pp(i + 3)] = f2tf32(v.w);
}
// encoder mem token: src rows have stride SENC_*D_, take first D_ of each row
__global__ void conv_enc(const float* __restrict__ src, uint32_t* __restrict__ dst) {
    int i = (blockIdx.x * blockDim.x + threadIdx.x) * 4;   // flat over B_*D_
    int row = i >> 9, k = i & (D_ - 1);
    float4 v = *(const float4*)(src + (size_t)row * (SENC_ * D_) + k);
    dst[pp(i + 0)] = f2tf32(v.x);
    dst[pp(i + 1)] = f2tf32(v.y);
    dst[pp(i + 2)] = f2tf32(v.z);
    dst[pp(i + 3)] = f2tf32(v.w);
}

// ---- TF32 GEMM on pre-converted permuted operands.
// C[Nrows, M] = A[Nrows, K] @ W[M, K]^T + bias. operm: store permuted tf32 to u32 C.
// CTA 128x128, 256 threads = 8 warps, warp tile 32x64, cp.async 3-stage ring.
// Nrows % 128 == 0, K % 32 == 0; M % 128 == 0 required when operm.
__global__ __launch_bounds__(256, 2) void tgemm(
    int M, int K,
    const uint32_t* __restrict__ A, const uint32_t* __restrict__ W,
    const float* __restrict__ bias, void* __restrict__ Cv, int relu, int operm)
{
    extern __shared__ uint32_t sm[];
    const uint32_t sb = smem_u32(sm);
    const int tid = threadIdx.x;
    const int wid = tid >> 5, lane = tid & 31;
    const int g = lane >> 2, tig = lane & 3;
    const int wm = (wid & 3) * 32;
    const int wn = (wid >> 2) * 64;
    const int bm = blockIdx.y * 128;
    const int bn = blockIdx.x * 128;

    float acc[2][8][4];
#pragma unroll
    for (int i = 0; i < 2; i++)
#pragma unroll
        for (int j = 0; j < 8; j++)
#pragma unroll
            for (int r = 0; r < 4; r++) acc[i][j][r] = 0.f;

    // staging: threads 0..127 copy A row, 128..255 copy B row (32 u32 = 8 cp16 each)
    const int srow = tid & 127;
    const bool isA = tid < 128;
    const bool bok = isA || ((bn + srow) < M);
    const uint32_t* src = isA ? (A + (size_t)(bm + srow) * K)
                              : (W + (size_t)((bn + srow) < M ? (bn + srow) : 0) * K);
    const uint32_t dst0 = sb + (uint32_t)((isA ? 0 : ABUF_U) + srow * RS) * 4u;

    const int nblk = K >> 5;

#pragma unroll
    for (int st = 0; st < 2; st++) {
        const uint32_t soff = (uint32_t)(st * STG_U) * 4u;
        const int kt = st * 32;
#pragma unroll
        for (int q = 0; q < 8; q++) cp16(dst0 + soff + q * 16u, src + kt + q * 4, bok);
        CP_COMMIT();
    }

    int buf = 0;
    for (int b = 0; b < nblk; b++) {
        if (b + 1 < nblk) asm volatile("cp.async.wait_group 1;" ::: "memory");
        else              asm volatile("cp.async.wait_group 0;" ::: "memory");
        __syncthreads();

        if (b + 2 < nblk) {
            int nb = buf + 2; if (nb >= 3) nb -= 3;
            const uint32_t soff = (uint32_t)(nb * STG_U) * 4u;
            const int kt = (b + 2) * 32;
#pragma unroll
            for (int q = 0; q < 8; q++) cp16(dst0 + soff + q * 16u, src + kt + q * 4, bok);
            CP_COMMIT();
        }

        const uint32_t* As_ = sm + buf * STG_U;
        const uint32_t* Bs_ = As_ + ABUF_U;
#pragma unroll
        for (int kp = 0; kp < 2; kp++) {
            uint4 av[4];
#pragma unroll
            for (int i = 0; i < 2; i++) {
                av[2 * i]     = *(const uint4*)(As_ + (wm + 16 * i + g) * RS + tig * 8 + kp * 4);
                av[2 * i + 1] = *(const uint4*)(As_ + (wm + 16 * i + g + 8) * RS + tig * 8 + kp * 4);
            }
#pragma unroll
            for (int jh = 0; jh < 2; jh++) {
                uint4 bv[4];
#pragma unroll
                for (int j = 0; j < 4; j++)
                    bv[j] = *(const uint4*)(Bs_ + (wn + 8 * (jh * 4 + j) + g) * RS + tig * 8 + kp * 4);
#pragma unroll
                for (int i = 0; i < 2; i++) {
                    uint32_t a0[4] = {av[2 * i].x, av[2 * i + 1].x, av[2 * i].y, av[2 * i + 1].y};
                    uint32_t a1[4] = {av[2 * i].z, av[2 * i + 1].z, av[2 * i].w, av[2 * i + 1].w};
#pragma unroll
                    for (int j = 0; j < 4; j++) {
                        uint32_t b0[2] = {bv[j].x, bv[j].y};
                        mma_tf32(acc[i][jh * 4 + j], a0, b0);
                        uint32_t b1[2] = {bv[j].z, bv[j].w};
                        mma_tf32(acc[i][jh * 4 + j], a1, b1);
                    }
                }
            }
        }
        buf++; if (buf == 3) buf = 0;
    }

    // epilogue: acc[i][j][{2h,2h+1}] -> row bm+wm+16i+g+8h, cols bn+wn+8j+2tig+{0,1}
    const bool meven = (M & 1) == 0;
#pragma unroll
    for (int i = 0; i < 2; i++) {
        const int r0 = bm + wm + 16 * i + g;
#pragma unroll
        for (int j = 0; j < 8; j++) {
            const int col = bn + wn + 8 * j + 2 * tig;
            const float bz0 = bias ? bias[col < M ? col : 0] : 0.f;
            const float bz1 = bias ? bias[(col + 1) < M ? (col + 1) : 0] : 0.f;
#pragma unroll
            for (int h = 0; h < 2; h++) {
                const int row = r0 + h * 8;
                float v0 = acc[i][j][2 * h + 0] + bz0;
                float v1 = acc[i][j][2 * h + 1] + bz1;
                if (relu) { v0 = fmaxf(v0, 0.f); v1 = fmaxf(v1, 0.f); }
                if (operm) {
                    uint32_t* C = (uint32_t*)Cv + (size_t)row * M;
                    C[pp(col)]     = f2tf32(v0);
                    C[pp(col + 1)] = f2tf32(v1);
                } else {
                    float* cp = (float*)Cv + (size_t)row * M + col;
                    if (col + 1 < M) {
                        if (meven) { float2 o = make_float2(v0, v1); *(float2*)cp = o; }
                        else       { cp[0] = v0; cp[1] = v1; }
                    } else if (col < M) {
                        *cp = v0;
                    }
                }
            }
        }
    }
}

// ---------------- embedding + mask (emits fp32 x and permuted tf32 xp) -------
__global__ void embed_kernel(const float* __restrict__ emb,
                             const float* __restrict__ point,
                             const float* __restrict__ pos,
                             const int*   __restrict__ tgt,
                             float* __restrict__ x,
                             uint32_t* __restrict__ xp,
                             float* __restrict__ padmask) {
    int n = blockIdx.x;
    int b = n / L_, l = n % L_;
    int tok = tgt[b * (L_ + 1) + l];
    if (threadIdx.x == 0) padmask[n] = (tok == PAD_ID) ? -1e30f : 0.0f;
    int t = threadIdx.x;
    float4 e  = ((const float4*)(emb   + (size_t)tok * D_))[t];
    float4 p  = ((const float4*)(point + (size_t)b   * D_))[t];
    float4 ps = ((const float4*)(pos   + (size_t)l   * D_))[t];
    float4 o;
    o.x = e.x + p.x + ps.x; o.y = e.y + p.y + ps.y;
    o.z = e.z + p.z + ps.z; o.w = e.w + p.w + ps.w;
    ((float4*)(x + (size_t)n * D_))[t] = o;
    uint32_t* xr = xp + (size_t)n * D_;
    int d0 = 4 * t;
    xr[pp(d0 + 0)] = f2tf32(o.x);
    xr[pp(d0 + 1)] = f2tf32(o.y);
    xr[pp(d0 + 2)] = f2tf32(o.z);
    xr[pp(d0 + 3)] = f2tf32(o.w);
}

// ---------------- causal self-attention; output permuted tf32 ----------------
__global__ __launch_bounds__(64) void attn_kernel(const float* __restrict__ qkv,
                            const float* __restrict__ padmask,
                            uint32_t* __restrict__ ap) {
    __shared__ float ks[L_][HD_];
    __shared__ float vs[L_][HD_];
    int b = blockIdx.x / NH_, h = blockIdx.x % NH_;
    const float* base = qkv + (size_t)b * L_ * (3 * D_) + h * HD_;
    for (int idx = threadIdx.x; idx < L_ * HD_; idx += 64) {
        int l = idx >> 6, d = idx & 63;
        ks[l][d] = base[(size_t)l * (3 * D_) + D_ + d];
        vs[l][d] = base[(size_t)l * (3 * D_) + 2 * D_ + d];
    }
    __syncthreads();
    int q = threadIdx.x;
    if (q >= L_) return;
    float qr[HD_];
    const float* qrow = base + (size_t)q * (3 * D_);
#pragma unroll
    for (int d = 0; d < HD_; d++) qr[d] = qrow[d];
    float m = -1e30f, lsum = 0.f;
    float acc[HD_];
#pragma unroll
    for (int d = 0; d < HD_; d++) acc[d] = 0.f;
    const float* pm = padmask + b * L_;
    for (int k = 0; k <= q; k++) {
        float s0 = 0.f, s1 = 0.f, s2 = 0.f, s3 = 0.f;
#pragma unroll
        for (int d = 0; d < HD_; d += 4) {
            s0 += qr[d + 0] * ks[k][d + 0];
            s1 += qr[d + 1] * ks[k][d + 1];
            s2 += qr[d + 2] * ks[k][d + 2];
            s3 += qr[d + 3] * ks[k][d + 3];
        }
        float s = ((s0 + s1) + (s2 + s3)) * 0.125f + pm[k];
        float mn = fmaxf(m, s);
        float corr = expf(m - mn);
        float e = expf(s - mn);
        lsum = lsum * corr + e;
#pragma unroll
        for (int d = 0; d < HD_; d++) acc[d] = acc[d] * corr + e * vs[k][d];
        m = mn;
    }
    float inv = 1.0f / lsum;
    uint32_t* arow = ap + (size_t)(b * L_ + q) * D_;
#pragma unroll
    for (int d = 0; d < HD_; d++) arow[pp(h * HD_ + d)] = f2tf32(acc[d] * inv);
}

// ---------------- fused residual add + LayerNorm (optional permuted xp out) ---
__global__ __launch_bounds__(128) void add_ln_kernel(
                              float* __restrict__ x, const float* __restrict__ y, int ybatch,
                              const float* __restrict__ s, const float* __restrict__ b,
                              uint32_t* __restrict__ xp) {
    int n = blockIdx.x;
    float* xr = x + (size_t)n * D_;
    const float* yr = y + (size_t)(ybatch ? (n / L_) : n) * D_;
    int t = threadIdx.x;
    float4 xv = ((const float4*)xr)[t];
    float4 yv = ((const float4*)yr)[t];
    float v0 = xv.x + yv.x, v1 = xv.y + yv.y, v2 = xv.z + yv.z, v3 = xv.w + yv.w;
    float sum = v0 + v1 + v2 + v3;
    float sq  = v0 * v0 + v1 * v1 + v2 * v2 + v3 * v3;
#pragma unroll
    for (int off = 16; off > 0; off >>= 1) {
        sum += __shfl_xor_sync(0xffffffffu, sum, off);
        sq  += __shfl_xor_sync(0xffffffffu, sq,  off);
    }
    __shared__ float rs[4], rq[4];
    int wid = t >> 5, lane = t & 31;
    if (lane == 0) { rs[wid] = sum; rq[wid] = sq; }
    __syncthreads();
    sum = rs[0] + rs[1] + rs[2] + rs[3];
    sq  = rq[0] + rq[1] + rq[2] + rq[3];
    float mean = sum * (1.0f / D_);
    float var  = sq  * (1.0f / D_) - mean * mean;
    float rstd = rsqrtf(var + 1e-5f);
    float4 sv = ((const float4*)s)[t];
    float4 bv = ((const float4*)b)[t];
    float4 o;
    o.x = (v0 - mean) * rstd * sv.x + bv.x;
    o.y = (v1 - mean) * rstd * sv.y + bv.y;
    o.z = (v2 - mean) * rstd * sv.z + bv.z;
    o.w = (v3 - mean) * rstd * sv.w + bv.w;
    ((float4*)xr)[t] = o;
    if (xp) {
        uint32_t* xpr = xp + (size_t)n * D_;
        int d0 = 4 * t;
        xpr[pp(d0 + 0)] = f2tf32(o.x);
        xpr[pp(d0 + 1)] = f2tf32(o.y);
        xpr[pp(d0 + 2)] = f2tf32(o.z);
        xpr[pp(d0 + 3)] = f2tf32(o.w);
    }
}

// ---------------- launch ----------------
static inline void launch_gemm(int Nrows, int M, int K,
                               const uint32_t* A, const uint32_t* W,
                               const float* bias, void* C, int relu, int operm) {
    dim3 g((M + 127) / 128, Nrows / 128);
    tgemm<<<g, 256, SM_BYTES>>>(M, K, A, W, bias, C, relu, operm);
}
static inline void launch_conv(const float* src, uint32_t* dst, int total) {
    conv_perm<<<(total / 4 + 255) / 256, 256>>>(src, dst, total);
}

extern "C" void kernel_launch(void* const* d_in, const int* in_sizes, int n_in,
                              void* d_out, int out_size) {
    const float* encoder_out = (const float*)d_in[0];
    const float* point_out   = (const float*)d_in[1];
    const float* emb         = (const float*)d_in[2];
    const float* pos_embed   = (const float*)d_in[3];
    const float* sa_inw      = (const float*)d_in[4];
    const float* sa_inb      = (const float*)d_in[5];
    const float* sa_outw     = (const float*)d_in[6];
    const float* sa_outb     = (const float*)d_in[7];
    const float* ca_inw      = (const float*)d_in[8];
    const float* ca_inb      = (const float*)d_in[9];
    const float* ca_outw     = (const float*)d_in[10];
    const float* ca_outb     = (const float*)d_in[11];
    const float* ln1_s       = (const float*)d_in[12];
    const float* ln1_b       = (const float*)d_in[13];
    const float* ln2_s       = (const float*)d_in[14];
    const float* ln2_b       = (const float*)d_in[15];
    const float* ln3_s       = (const float*)d_in[16];
    const float* ln3_b       = (const float*)d_in[17];
    const float* ff1_w       = (const float*)d_in[18];
    const float* ff1_b       = (const float*)d_in[19];
    const float* ff2_w       = (const float*)d_in[20];
    const float* ff2_b       = (const float*)d_in[21];
    const float* out_w       = (const float*)d_in[22];
    const float* out_b       = (const float*)d_in[23];
    const int*   tgt         = (const int*)d_in[24];

    cudaFuncSetAttribute(tgemm, cudaFuncAttributeMaxDynamicSharedMemorySize, SM_BYTES);

    float *x, *t, *qkv, *yca, *pm;
    uint32_t *h, *xp, *ap, *ep, *vmemp;
    uint32_t *w1, *w2, *w3, *w4, *w5, *w6, *w7;
    cudaGetSymbolAddress((void**)&x,    g_x);
    cudaGetSymbolAddress((void**)&t,    g_t);
    cudaGetSymbolAddress((void**)&qkv,  g_qkv);
    cudaGetSymbolAddress((void**)&h,    g_h);
    cudaGetSymbolAddress((void**)&yca,  g_yca);
    cudaGetSymbolAddress((void**)&pm,   g_padmask);
    cudaGetSymbolAddress((void**)&xp,   g_xp);
    cudaGetSymbolAddress((void**)&ap,   g_ap);
    cudaGetSymbolAddress((void**)&ep,   g_ep);
    cudaGetSymbolAddress((void**)&vmemp, g_vmemp);
    cudaGetSymbolAddress((void**)&w1, g_w_sain);
    cudaGetSymbolAddress((void**)&w2, g_w_saout);
    cudaGetSymbolAddress((void**)&w3, g_w_cain);
    cudaGetSymbolAddress((void**)&w4, g_w_caout);
    cudaGetSymbolAddress((void**)&w5, g_w_ff1);
    cudaGetSymbolAddress((void**)&w6, g_w_ff2);
    cudaGetSymbolAddress((void**)&w7, g_w_out);

    // one-time (per launch) weight conversion to permuted tf32
    launch_conv(sa_inw,  w1, NL_ * 3 * D_ * D_);
    launch_conv(sa_outw, w2, NL_ * D_ * D_);
    launch_conv(ca_inw,  w3, NL_ * 3 * D_ * D_);
    launch_conv(ca_outw, w4, NL_ * D_ * D_);
    launch_conv(ff1_w,   w5, NL_ * DFF_ * D_);
    launch_conv(ff2_w,   w6, NL_ * D_ * DFF_);
    launch_conv(out_w,   w7, VOCAB * D_);
    conv_enc<<<(B_ * D_ / 4 + 255) / 256, 256>>>(encoder_out, ep);

    embed_kernel<<<NTOK, 128>>>(emb, point_out, pos_embed, tgt, x, xp, pm);

    for (int i = 0; i < NL_; i++) {
        const uint32_t* w_qkv = w1 + (size_t)i * 3 * D_ * D_;
        const uint32_t* w_so  = w2 + (size_t)i * D_ * D_;
        const uint32_t* w_cv  = w3 + ((size_t)i * 3 * D_ + 2 * D_) * D_;  // V slice
        const uint32_t* w_co  = w4 + (size_t)i * D_ * D_;
        const uint32_t* w_f1  = w5 + (size_t)i * DFF_ * D_;
        const uint32_t* w_f2  = w6 + (size_t)i * D_ * DFF_;

        // ---- self attention ----
        launch_gemm(NTOK, 3 * D_, D_, xp, w_qkv, sa_inb + i * 3 * D_, qkv, 0, 0);
        attn_kernel<<<B_ * NH_, 64>>>(qkv, pm, ap);
        launch_gemm(NTOK, D_, D_, ap, w_so, sa_outb + i * D_, t, 0, 0);
        add_ln_kernel<<<NTOK, 128>>>(x, t, 0, ln1_s + i * D_, ln1_b + i * D_, nullptr);

        // ---- cross attention (single memory token: output = V(mem) @ Wout + b,
        //      constant over query positions; Q/K provably irrelevant) ----
        launch_gemm(B_, D_, D_, ep, w_cv, ca_inb + i * 3 * D_ + 2 * D_, vmemp, 0, 1);
        launch_gemm(B_, D_, D_, vmemp, w_co, ca_outb + i * D_, yca, 0, 0);
        add_ln_kernel<<<NTOK, 128>>>(x, yca, 1, ln2_s + i * D_, ln2_b + i * D_, xp);

        // ---- FFN ----
        launch_gemm(NTOK, DFF_, D_, xp, w_f1, ff1_b + i * DFF_, h, 1, 1);
        launch_gemm(NTOK, D_, DFF_, h, w_f2, ff2_b + i * D_, t, 0, 0);
        add_ln_kernel<<<NTOK, 128>>>(x, t, 0, ln3_s + i * D_, ln3_b + i * D_, xp);
    }

    // ---- final logits ----
    launch_gemm(NTOK, VOCAB, D_, xp, w7, out_b, (float*)d_out, 0, 0);
}

// round 16
// speedup vs baseline: 1.2787x; 1.2787x over previous
#include <cuda_runtime.h>
#include <cuda_bf16.h>
#include <cstdint>

#define D_     512
#define NH_    8
#define HD_    64
#define NL_    6
#define DFF_   2048
#define VOCAB  1027
#define PAD_ID 1026
#define B_     256
#define SENC_  16
#define L_     61
#define NTOK   (B_ * L_)   // 15616 = 122 * 128

// ---------------- device scratch ----------------
__device__ float g_x[NTOK * D_];
__device__ float g_t[NTOK * D_];
__device__ float g_qkv[NTOK * 3 * D_];
__device__ float g_h[(size_t)NTOK * DFF_];   // ffn hidden / attn-out scratch
__device__ float g_vmem[B_ * D_];
__device__ float g_yca[B_ * D_];
__device__ float g_padmask[NTOK];

// ---------------- helpers ----------------
__device__ __forceinline__ uint32_t smem_u32(const void* p) {
    uint32_t a;
    asm("{ .reg .u64 t; cvta.to.shared.u64 t, %1; cvt.u32.u64 %0, t; }" : "=r"(a) : "l"(p));
    return a;
}
__device__ __forceinline__ uint32_t f2tf32(float f) {
    uint32_t u; asm("cvt.rna.tf32.f32 %0, %1;" : "=r"(u) : "f"(f)); return u;
}
__device__ __forceinline__ void mma_tf32(float* c, const uint32_t* a, const uint32_t* b) {
    asm volatile(
        "mma.sync.aligned.m16n8k8.row.col.f32.tf32.tf32.f32 "
        "{%0,%1,%2,%3}, {%4,%5,%6,%7}, {%8,%9}, {%0,%1,%2,%3};"
        : "+f"(c[0]), "+f"(c[1]), "+f"(c[2]), "+f"(c[3])
        : "r"(a[0]), "r"(a[1]), "r"(a[2]), "r"(a[3]), "r"(b[0]), "r"(b[1]));
}
__device__ __forceinline__ void cp16(uint32_t dst, const void* src, bool ok) {
    int sz = ok ? 16 : 0;
    asm volatile("cp.async.ca.shared.global [%0], [%1], 16, %2;"
                 :: "r"(dst), "l"(src), "r"(sz));
}
#define CP_COMMIT() asm volatile("cp.async.commit_group;" ::: "memory")

// smem geometry (floats): row stride 36. A: 128 rows, B: 256 rows. 3 stages.
#define RS      36
#define ABUF_F  (128 * RS)            // 4608
#define BBUF_F  (256 * RS)            // 9216
#define STG_F   (ABUF_F + BBUF_F)     // 13824 floats = 55296 B / stage
#define SM_BYTES (3 * STG_F * 4)      // 165888 bytes

// ---- TF32 GEMM: C[Nrows, M] = A[Nrows, K](row stride lda) @ W[M, K]^T + bias
// CTA tile 128x256, 256 threads = 8 warps (2x4), warp tile 64x64, BK=32,
// cp.async 3-stage ring. Nrows % 128 == 0, K % 64 == 0. M ragged OK.
__global__ __launch_bounds__(256) void tgemm(
    int M, int K, int lda,
    const float* __restrict__ A, const float* __restrict__ W,
    const float* __restrict__ bias, float* __restrict__ C, int relu)
{
    extern __shared__ float sm[];
    const uint32_t sb = smem_u32(sm);
    const int tid = threadIdx.x;
    const int wid = tid >> 5, lane = tid & 31;
    const int g = lane >> 2, tig = lane & 3;
    const int wm = (wid & 1) * 64;        // 2 row-groups of 64
    const int wn = (wid >> 1) * 64;       // 4 col-groups of 64
    const int bm = blockIdx.y * 128;
    const int bn = blockIdx.x * 256;

    float acc[4][8][4];
#pragma unroll
    for (int i = 0; i < 4; i++)
#pragma unroll
        for (int j = 0; j < 8; j++)
#pragma unroll
            for (int r = 0; r < 4; r++) acc[i][j][r] = 0.f;

    // staging: A row tid>>1 (half-row: 4 cp16), B row tid (8 cp16) -> 12 cp16/thread
    const int arow = tid >> 1;
    const int aseg = (tid & 1) * 4;       // which 16-float half
    const float* Asrc = A + (size_t)(bm + arow) * lda + aseg * 4;
    const bool bok = (bn + tid) < M;
    const float* Wsrc = W + (size_t)(bok ? (bn + tid) : 0) * K;
    const uint32_t adst = sb + (uint32_t)(arow * RS + aseg * 4) * 4u;
    const uint32_t bdst = sb + (uint32_t)(ABUF_F + tid * RS) * 4u;

    const int nblk = K >> 5;

#pragma unroll
    for (int st = 0; st < 2; st++) {
        const uint32_t soff = (uint32_t)(st * STG_F) * 4u;
        const int kt = st * 32;
#pragma unroll
        for (int q = 0; q < 4; q++) cp16(adst + soff + q * 16u, Asrc + kt + q * 4, true);
#pragma unroll
        for (int q = 0; q < 8; q++) cp16(bdst + soff + q * 16u, Wsrc + kt + q * 4, bok);
        CP_COMMIT();
    }

    int buf = 0;
    for (int b = 0; b < nblk; b++) {
        if (b + 1 < nblk) asm volatile("cp.async.wait_group 1;" ::: "memory");
        else              asm volatile("cp.async.wait_group 0;" ::: "memory");
        __syncthreads();

        if (b + 2 < nblk) {
            int nb = buf + 2; if (nb >= 3) nb -= 3;
            const uint32_t soff = (uint32_t)(nb * STG_F) * 4u;
            const int kt = (b + 2) * 32;
#pragma unroll
            for (int q = 0; q < 4; q++) cp16(adst + soff + q * 16u, Asrc + kt + q * 4, true);
#pragma unroll
            for (int q = 0; q < 8; q++) cp16(bdst + soff + q * 16u, Wsrc + kt + q * 4, bok);
            CP_COMMIT();
        }

        const float* As_ = sm + buf * STG_F;
        const float* Bs_ = As_ + ABUF_F;
#pragma unroll
        for (int ks = 0; ks < 4; ks++) {
            const int k0 = ks * 8;
            uint32_t af[4][4], bf[8][2];
#pragma unroll
            for (int i = 0; i < 4; i++) {
                const int r0 = (wm + 16 * i + g) * RS;
                const int r1 = (wm + 16 * i + g + 8) * RS;
                af[i][0] = f2tf32(As_[r0 + k0 + tig]);
                af[i][1] = f2tf32(As_[r1 + k0 + tig]);
                af[i][2] = f2tf32(As_[r0 + k0 + tig + 4]);
                af[i][3] = f2tf32(As_[r1 + k0 + tig + 4]);
            }
#pragma unroll
            for (int j = 0; j < 8; j++) {
                const int rb = (wn + 8 * j + g) * RS;
                bf[j][0] = f2tf32(Bs_[rb + k0 + tig]);
                bf[j][1] = f2tf32(Bs_[rb + k0 + tig + 4]);
            }
#pragma unroll
            for (int i = 0; i < 4; i++)
#pragma unroll
                for (int j = 0; j < 8; j++) mma_tf32(acc[i][j], af[i], bf[j]);
        }
        buf++; if (buf == 3) buf = 0;
    }

    const bool meven = (M & 1) == 0;
#pragma unroll
    for (int i = 0; i < 4; i++) {
        const int r0 = bm + wm + 16 * i + g;
#pragma unroll
        for (int j = 0; j < 8; j++) {
            const int col = bn + wn + 8 * j + 2 * tig;
            const float bz0 = bias ? bias[col < M ? col : 0] : 0.f;
            const float bz1 = bias ? bias[(col + 1) < M ? (col + 1) : 0] : 0.f;
#pragma unroll
            for (int h = 0; h < 2; h++) {
                const int row = r0 + h * 8;
                float v0 = acc[i][j][2 * h + 0] + bz0;
                float v1 = acc[i][j][2 * h + 1] + bz1;
                if (relu) { v0 = fmaxf(v0, 0.f); v1 = fmaxf(v1, 0.f); }
                float* cp = C + (size_t)row * M + col;
                if (col + 1 < M) {
                    if (meven) { float2 o = make_float2(v0, v1); *(float2*)cp = o; }
                    else       { cp[0] = v0; cp[1] = v1; }
                } else if (col < M) {
                    *cp = v0;
                }
            }
        }
    }
}

// ---------------- embedding + mask ----------------
__global__ void embed_kernel(const float* __restrict__ emb,
                             const float* __restrict__ point,
                             const float* __restrict__ pos,
                             const int*   __restrict__ tgt,
                             float* __restrict__ x,
                             float* __restrict__ padmask) {
    int n = blockIdx.x;
    int b = n / L_, l = n % L_;
    int tok = tgt[b * (L_ + 1) + l];
    if (threadIdx.x == 0) padmask[n] = (tok == PAD_ID) ? -1e30f : 0.0f;
    int t = threadIdx.x;
    float4 e  = ((const float4*)(emb   + (size_t)tok * D_))[t];
    float4 p  = ((const float4*)(point + (size_t)b   * D_))[t];
    float4 ps = ((const float4*)(pos   + (size_t)l   * D_))[t];
    float4 o;
    o.x = e.x + p.x + ps.x; o.y = e.y + p.y + ps.y;
    o.z = e.z + p.z + ps.z; o.w = e.w + p.w + ps.w;
    ((float4*)(x + (size_t)n * D_))[t] = o;
}

// ---------------- causal self-attention, one block per (b, h) ----------------
__global__ __launch_bounds__(64) void attn_kernel(const float* __restrict__ qkv,
                            const float* __restrict__ padmask,
                            float* __restrict__ o) {
    __shared__ float ks[L_][HD_];
    __shared__ float vs[L_][HD_];
    int b = blockIdx.x / NH_, h = blockIdx.x % NH_;
    const float* base = qkv + (size_t)b * L_ * (3 * D_) + h * HD_;
    for (int idx = threadIdx.x; idx < L_ * HD_; idx += 64) {
        int l = idx >> 6, d = idx & 63;
        ks[l][d] = base[(size_t)l * (3 * D_) + D_ + d];
        vs[l][d] = base[(size_t)l * (3 * D_) + 2 * D_ + d];
    }
    __syncthreads();
    int q = threadIdx.x;
    if (q >= L_) return;
    float qr[HD_];
    const float* qrow = base + (size_t)q * (3 * D_);
#pragma unroll
    for (int d = 0; d < HD_; d++) qr[d] = qrow[d];
    float m = -1e30f, lsum = 0.f;
    float acc[HD_];
#pragma unroll
    for (int d = 0; d < HD_; d++) acc[d] = 0.f;
    const float* pm = padmask + b * L_;
    for (int k = 0; k <= q; k++) {
        float s0 = 0.f, s1 = 0.f, s2 = 0.f, s3 = 0.f;
#pragma unroll
        for (int d = 0; d < HD_; d += 4) {
            s0 += qr[d + 0] * ks[k][d + 0];
            s1 += qr[d + 1] * ks[k][d + 1];
            s2 += qr[d + 2] * ks[k][d + 2];
            s3 += qr[d + 3] * ks[k][d + 3];
        }
        float s = ((s0 + s1) + (s2 + s3)) * 0.125f + pm[k];
        float mn = fmaxf(m, s);
        float corr = expf(m - mn);
        float e = expf(s - mn);
        lsum = lsum * corr + e;
#pragma unroll
        for (int d = 0; d < HD_; d++) acc[d] = acc[d] * corr + e * vs[k][d];
        m = mn;
    }
    float inv = 1.0f / lsum;
    float* orow = o + (size_t)(b * L_ + q) * D_ + h * HD_;
#pragma unroll
    for (int d = 0; d < HD_; d++) orow[d] = acc[d] * inv;
}

// ---------------- fused residual add + LayerNorm ----------------
__global__ __launch_bounds__(128) void add_ln_kernel(
                              float* __restrict__ x, const float* __restrict__ y, int ybatch,
                              const float* __restrict__ s, const float* __restrict__ b) {
    int n = blockIdx.x;
    float* xr = x + (size_t)n * D_;
    const float* yr = y + (size_t)(ybatch ? (n / L_) : n) * D_;
    int t = threadIdx.x;
    float4 xv = ((const float4*)xr)[t];
    float4 yv = ((const float4*)yr)[t];
    float v0 = xv.x + yv.x, v1 = xv.y + yv.y, v2 = xv.z + yv.z, v3 = xv.w + yv.w;
    float sum = v0 + v1 + v2 + v3;
    float sq  = v0 * v0 + v1 * v1 + v2 * v2 + v3 * v3;
#pragma unroll
    for (int off = 16; off > 0; off >>= 1) {
        sum += __shfl_xor_sync(0xffffffffu, sum, off);
        sq  += __shfl_xor_sync(0xffffffffu, sq,  off);
    }
    __shared__ float rs[4], rq[4];
    int wid = t >> 5, lane = t & 31;
    if (lane == 0) { rs[wid] = sum; rq[wid] = sq; }
    __syncthreads();
    sum = rs[0] + rs[1] + rs[2] + rs[3];
    sq  = rq[0] + rq[1] + rq[2] + rq[3];
    float mean = sum * (1.0f / D_);
    float var  = sq  * (1.0f / D_) - mean * mean;
    float rstd = rsqrtf(var + 1e-5f);
    float4 sv = ((const float4*)s)[t];
    float4 bv = ((const float4*)b)[t];
    float4 o;
    o.x = (v0 - mean) * rstd * sv.x + bv.x;
    o.y = (v1 - mean) * rstd * sv.y + bv.y;
    o.z = (v2 - mean) * rstd * sv.z + bv.z;
    o.w = (v3 - mean) * rstd * sv.w + bv.w;
    ((float4*)xr)[t] = o;
}

// ---------------- launch ----------------
static inline void launch_gemm(int Nrows, int M, int K, int lda,
                               const float* A, const float* W,
                               const float* bias, float* C, int relu) {
    dim3 g((M + 255) / 256, Nrows / 128);
    tgemm<<<g, 256, SM_BYTES>>>(M, K, lda, A, W, bias, C, relu);
}

extern "C" void kernel_launch(void* const* d_in, const int* in_sizes, int n_in,
                              void* d_out, int out_size) {
    const float* encoder_out = (const float*)d_in[0];
    const float* point_out   = (const float*)d_in[1];
    const float* emb         = (const float*)d_in[2];
    const float* pos_embed   = (const float*)d_in[3];
    const float* sa_inw      = (const float*)d_in[4];
    const float* sa_inb      = (const float*)d_in[5];
    const float* sa_outw     = (const float*)d_in[6];
    const float* sa_outb     = (const float*)d_in[7];
    const float* ca_inw      = (const float*)d_in[8];
    const float* ca_inb      = (const float*)d_in[9];
    const float* ca_outw     = (const float*)d_in[10];
    const float* ca_outb     = (const float*)d_in[11];
    const float* ln1_s       = (const float*)d_in[12];
    const float* ln1_b       = (const float*)d_in[13];
    const float* ln2_s       = (const float*)d_in[14];
    const float* ln2_b       = (const float*)d_in[15];
    const float* ln3_s       = (const float*)d_in[16];
    const float* ln3_b       = (const float*)d_in[17];
    const float* ff1_w       = (const float*)d_in[18];
    const float* ff1_b       = (const float*)d_in[19];
    const float* ff2_w       = (const float*)d_in[20];
    const float* ff2_b       = (const float*)d_in[21];
    const float* out_w       = (const float*)d_in[22];
    const float* out_b       = (const float*)d_in[23];
    const int*   tgt         = (const int*)d_in[24];

    cudaFuncSetAttribute(tgemm, cudaFuncAttributeMaxDynamicSharedMemorySize, SM_BYTES);

    float *x, *t, *qkv, *h, *vmem, *yca, *pm;
    cudaGetSymbolAddress((void**)&x,    g_x);
    cudaGetSymbolAddress((void**)&t,    g_t);
    cudaGetSymbolAddress((void**)&qkv,  g_qkv);
    cudaGetSymbolAddress((void**)&h,    g_h);
    cudaGetSymbolAddress((void**)&vmem, g_vmem);
    cudaGetSymbolAddress((void**)&yca,  g_yca);
    cudaGetSymbolAddress((void**)&pm,   g_padmask);

    embed_kernel<<<NTOK, 128>>>(emb, point_out, pos_embed, tgt, x, pm);

    for (int i = 0; i < NL_; i++) {
        const float* sa_w_i   = sa_inw  + (size_t)i * 3 * D_ * D_;
        const float* sa_b_i   = sa_inb  + (size_t)i * 3 * D_;
        const float* sa_ow_i  = sa_outw + (size_t)i * D_ * D_;
        const float* sa_ob_i  = sa_outb + (size_t)i * D_;
        const float* ca_wv_i  = ca_inw  + ((size_t)i * 3 * D_ + 2 * D_) * D_;  // V slice
        const float* ca_bv_i  = ca_inb  + (size_t)i * 3 * D_ + 2 * D_;
        const float* ca_ow_i  = ca_outw + (size_t)i * D_ * D_;
        const float* ca_ob_i  = ca_outb + (size_t)i * D_;
        const float* f1w_i    = ff1_w   + (size_t)i * DFF_ * D_;
        const float* f1b_i    = ff1_b   + (size_t)i * DFF_;
        const float* f2w_i    = ff2_w   + (size_t)i * D_ * DFF_;
        const float* f2b_i    = ff2_b   + (size_t)i * D_;

        // ---- self attention ----
        launch_gemm(NTOK, 3 * D_, D_, D_, x, sa_w_i, sa_b_i, qkv, 0);
        attn_kernel<<<B_ * NH_, 64>>>(qkv, pm, h);
        launch_gemm(NTOK, D_, D_, D_, h, sa_ow_i, sa_ob_i, t, 0);
        add_ln_kernel<<<NTOK, 128>>>(x, t, 0, ln1_s + i * D_, ln1_b + i * D_);

        // ---- cross attention (single memory token: output = V(mem) @ Wout + b,
        //      constant over query positions; Q/K provably irrelevant) ----
        launch_gemm(B_, D_, D_, SENC_ * D_, encoder_out, ca_wv_i, ca_bv_i, vmem, 0);
        launch_gemm(B_, D_, D_, D_, vmem, ca_ow_i, ca_ob_i, yca, 0);
        add_ln_kernel<<<NTOK, 128>>>(x, yca, 1, ln2_s + i * D_, ln2_b + i * D_);

        // ---- FFN ----
        launch_gemm(NTOK, DFF_, D_, D_, x, f1w_i, f1b_i, h, 1);
        launch_gemm(NTOK, D_, DFF_, DFF_, h, f2w_i, f2b_i, t, 0);
        add_ln_kernel<<<NTOK, 128>>>(x, t, 0, ln3_s + i * D_, ln3_b + i * D_);
    }

    // ---- final logits ----
    launch_gemm(NTOK, VOCAB, D_, D_, x, out_w, out_b, (float*)d_out, 0);
}

// round 17
// speedup vs baseline: 1.2950x; 1.0127x over previous
#include <cuda_runtime.h>
#include <cuda_bf16.h>
#include <cstdint>

#define D_     512
#define NH_    8
#define HD_    64
#define NL_    6
#define DFF_   2048
#define VOCAB  1027
#define PAD_ID 1026
#define B_     256
#define SENC_  16
#define L_     61
#define NTOK   (B_ * L_)   // 15616 = 122 * 128

// ---------------- device scratch ----------------
__device__ float g_x[NTOK * D_];
__device__ float g_t[NTOK * D_];
__device__ float g_qkv[NTOK * 3 * D_];
__device__ float g_h[(size_t)NTOK * DFF_];   // ffn hidden / attn-out scratch
__device__ float g_vmem[B_ * D_];
__device__ float g_yca[B_ * D_];
__device__ float g_padmask[NTOK];

// ---------------- helpers ----------------
__device__ __forceinline__ uint32_t smem_u32(const void* p) {
    uint32_t a;
    asm("{ .reg .u64 t; cvta.to.shared.u64 t, %1; cvt.u32.u64 %0, t; }" : "=r"(a) : "l"(p));
    return a;
}
__device__ __forceinline__ uint32_t f2tf32(float f) {
    uint32_t u; asm("cvt.rna.tf32.f32 %0, %1;" : "=r"(u) : "f"(f)); return u;
}
__device__ __forceinline__ void mma_tf32(float* c, const uint32_t* a, const uint32_t* b) {
    asm volatile(
        "mma.sync.aligned.m16n8k8.row.col.f32.tf32.tf32.f32 "
        "{%0,%1,%2,%3}, {%4,%5,%6,%7}, {%8,%9}, {%0,%1,%2,%3};"
        : "+f"(c[0]), "+f"(c[1]), "+f"(c[2]), "+f"(c[3])
        : "r"(a[0]), "r"(a[1]), "r"(a[2]), "r"(a[3]), "r"(b[0]), "r"(b[1]));
}
// L2-resident async copy (bypass L1: staging data is single-use per CTA)
__device__ __forceinline__ void cp16(uint32_t dst, const void* src, bool ok) {
    int sz = ok ? 16 : 0;
    asm volatile("cp.async.cg.shared.global [%0], [%1], 16, %2;"
                 :: "r"(dst), "l"(src), "r"(sz));
}
#define CP_COMMIT() asm volatile("cp.async.commit_group;" ::: "memory")

// smem geometry (floats): row stride 36. A: 128 rows, B: 256 rows. 3 stages.
#define RS      36
#define ABUF_F  (128 * RS)            // 4608
#define BBUF_F  (256 * RS)            // 9216
#define STG_F   (ABUF_F + BBUF_F)     // 13824 floats = 55296 B / stage
#define SM_BYTES (3 * STG_F * 4)      // 165888 bytes

// ---- TF32 GEMM: C[Nrows, M] = A[Nrows, K](row stride lda) @ W[M, K]^T + bias
// CTA tile 128x256, 256 threads = 8 warps (2x4), warp tile 64x64, BK=32,
// cp.async 3-stage ring, register-double-buffered fragments.
// Nrows % 128 == 0, K % 64 == 0. M ragged OK.
__global__ __launch_bounds__(256) void tgemm(
    int M, int K, int lda,
    const float* __restrict__ A, const float* __restrict__ W,
    const float* __restrict__ bias, float* __restrict__ C, int relu)
{
    extern __shared__ float sm[];
    const uint32_t sb = smem_u32(sm);
    const int tid = threadIdx.x;
    const int wid = tid >> 5, lane = tid & 31;
    const int g = lane >> 2, tig = lane & 3;
    const int wm = (wid & 1) * 64;        // 2 row-groups of 64
    const int wn = (wid >> 1) * 64;       // 4 col-groups of 64
    const int bm = blockIdx.y * 128;
    const int bn = blockIdx.x * 256;

    float acc[4][8][4];
#pragma unroll
    for (int i = 0; i < 4; i++)
#pragma unroll
        for (int j = 0; j < 8; j++)
#pragma unroll
            for (int r = 0; r < 4; r++) acc[i][j][r] = 0.f;

    // staging: A row tid>>1 (half-row: 4 cp16), B row tid (8 cp16) -> 12 cp16/thread
    const int arow = tid >> 1;
    const int aseg = (tid & 1) * 4;       // which 16-float half
    const float* Asrc = A + (size_t)(bm + arow) * lda + aseg * 4;
    const bool bok = (bn + tid) < M;
    const float* Wsrc = W + (size_t)(bok ? (bn + tid) : 0) * K;
    const uint32_t adst = sb + (uint32_t)(arow * RS + aseg * 4) * 4u;
    const uint32_t bdst = sb + (uint32_t)(ABUF_F + tid * RS) * 4u;

    const int nblk = K >> 5;

#pragma unroll
    for (int st = 0; st < 2; st++) {
        const uint32_t soff = (uint32_t)(st * STG_F) * 4u;
        const int kt = st * 32;
#pragma unroll
        for (int q = 0; q < 4; q++) cp16(adst + soff + q * 16u, Asrc + kt + q * 4, true);
#pragma unroll
        for (int q = 0; q < 8; q++) cp16(bdst + soff + q * 16u, Wsrc + kt + q * 4, bok);
        CP_COMMIT();
    }

    uint32_t af[2][4][4], bf[2][8][2];   // double-buffered fragments

    int buf = 0;
    for (int b = 0; b < nblk; b++) {
        if (b + 1 < nblk) asm volatile("cp.async.wait_group 1;" ::: "memory");
        else              asm volatile("cp.async.wait_group 0;" ::: "memory");
        __syncthreads();

        if (b + 2 < nblk) {
            int nb = buf + 2; if (nb >= 3) nb -= 3;
            const uint32_t soff = (uint32_t)(nb * STG_F) * 4u;
            const int kt = (b + 2) * 32;
#pragma unroll
            for (int q = 0; q < 4; q++) cp16(adst + soff + q * 16u, Asrc + kt + q * 4, true);
#pragma unroll
            for (int q = 0; q < 8; q++) cp16(bdst + soff + q * 16u, Wsrc + kt + q * 4, bok);
            CP_COMMIT();
        }

        const float* As_ = sm + buf * STG_F;
        const float* Bs_ = As_ + ABUF_F;

        // preload ks=0 fragments into buffer 0
#pragma unroll
        for (int i = 0; i < 4; i++) {
            const int r0 = (wm + 16 * i + g) * RS;
            const int r1 = (wm + 16 * i + g + 8) * RS;
            af[0][i][0] = f2tf32(As_[r0 + tig]);
            af[0][i][1] = f2tf32(As_[r1 + tig]);
            af[0][i][2] = f2tf32(As_[r0 + tig + 4]);
            af[0][i][3] = f2tf32(As_[r1 + tig + 4]);
        }
#pragma unroll
        for (int j = 0; j < 8; j++) {
            const int rb = (wn + 8 * j + g) * RS;
            bf[0][j][0] = f2tf32(Bs_[rb + tig]);
            bf[0][j][1] = f2tf32(Bs_[rb + tig + 4]);
        }

#pragma unroll
        for (int ks = 0; ks < 4; ks++) {
            const int cur = ks & 1, nxt = cur ^ 1;
            if (ks < 3) {
                const int k0 = (ks + 1) * 8;
#pragma unroll
                for (int i = 0; i < 4; i++) {
                    const int r0 = (wm + 16 * i + g) * RS;
                    const int r1 = (wm + 16 * i + g + 8) * RS;
                    af[nxt][i][0] = f2tf32(As_[r0 + k0 + tig]);
                    af[nxt][i][1] = f2tf32(As_[r1 + k0 + tig]);
                    af[nxt][i][2] = f2tf32(As_[r0 + k0 + tig + 4]);
                    af[nxt][i][3] = f2tf32(As_[r1 + k0 + tig + 4]);
                }
#pragma unroll
                for (int j = 0; j < 8; j++) {
                    const int rb = (wn + 8 * j + g) * RS;
                    bf[nxt][j][0] = f2tf32(Bs_[rb + k0 + tig]);
                    bf[nxt][j][1] = f2tf32(Bs_[rb + k0 + tig + 4]);
                }
            }
#pragma unroll
            for (int i = 0; i < 4; i++)
#pragma unroll
                for (int j = 0; j < 8; j++) mma_tf32(acc[i][j], af[cur][i], bf[cur][j]);
        }
        buf++; if (buf == 3) buf = 0;
    }

    const bool meven = (M & 1) == 0;
#pragma unroll
    for (int i = 0; i < 4; i++) {
        const int r0 = bm + wm + 16 * i + g;
#pragma unroll
        for (int j = 0; j < 8; j++) {
            const int col = bn + wn + 8 * j + 2 * tig;
            const float bz0 = bias ? bias[col < M ? col : 0] : 0.f;
            const float bz1 = bias ? bias[(col + 1) < M ? (col + 1) : 0] : 0.f;
#pragma unroll
            for (int h = 0; h < 2; h++) {
                const int row = r0 + h * 8;
                float v0 = acc[i][j][2 * h + 0] + bz0;
                float v1 = acc[i][j][2 * h + 1] + bz1;
                if (relu) { v0 = fmaxf(v0, 0.f); v1 = fmaxf(v1, 0.f); }
                float* cp = C + (size_t)row * M + col;
                if (col + 1 < M) {
                    if (meven) { float2 o = make_float2(v0, v1); *(float2*)cp = o; }
                    else       { cp[0] = v0; cp[1] = v1; }
                } else if (col < M) {
                    *cp = v0;
                }
            }
        }
    }
}

// ---------------- embedding + mask ----------------
__global__ void embed_kernel(const float* __restrict__ emb,
                             const float* __restrict__ point,
                             const float* __restrict__ pos,
                             const int*   __restrict__ tgt,
                             float* __restrict__ x,
                             float* __restrict__ padmask) {
    int n = blockIdx.x;
    int b = n / L_, l = n % L_;
    int tok = tgt[b * (L_ + 1) + l];
    if (threadIdx.x == 0) padmask[n] = (tok == PAD_ID) ? -1e30f : 0.0f;
    int t = threadIdx.x;
    float4 e  = ((const float4*)(emb   + (size_t)tok * D_))[t];
    float4 p  = ((const float4*)(point + (size_t)b   * D_))[t];
    float4 ps = ((const float4*)(pos   + (size_t)l   * D_))[t];
    float4 o;
    o.x = e.x + p.x + ps.x; o.y = e.y + p.y + ps.y;
    o.z = e.z + p.z + ps.z; o.w = e.w + p.w + ps.w;
    ((float4*)(x + (size_t)n * D_))[t] = o;
}

// ---------------- causal self-attention, one block per (b, h) ----------------
__global__ __launch_bounds__(64) void attn_kernel(const float* __restrict__ qkv,
                            const float* __restrict__ padmask,
                            float* __restrict__ o) {
    __shared__ float ks[L_][HD_];
    __shared__ float vs[L_][HD_];
    int b = blockIdx.x / NH_, h = blockIdx.x % NH_;
    const float* base = qkv + (size_t)b * L_ * (3 * D_) + h * HD_;
    for (int idx = threadIdx.x; idx < L_ * HD_; idx += 64) {
        int l = idx >> 6, d = idx & 63;
        ks[l][d] = base[(size_t)l * (3 * D_) + D_ + d];
        vs[l][d] = base[(size_t)l * (3 * D_) + 2 * D_ + d];
    }
    __syncthreads();
    int q = threadIdx.x;
    if (q >= L_) return;
    float qr[HD_];
    const float* qrow = base + (size_t)q * (3 * D_);
#pragma unroll
    for (int d = 0; d < HD_; d++) qr[d] = qrow[d];
    float m = -1e30f, lsum = 0.f;
    float acc[HD_];
#pragma unroll
    for (int d = 0; d < HD_; d++) acc[d] = 0.f;
    const float* pm = padmask + b * L_;
    for (int k = 0; k <= q; k++) {
        float s0 = 0.f, s1 = 0.f, s2 = 0.f, s3 = 0.f;
#pragma unroll
        for (int d = 0; d < HD_; d += 4) {
            s0 += qr[d + 0] * ks[k][d + 0];
            s1 += qr[d + 1] * ks[k][d + 1];
            s2 += qr[d + 2] * ks[k][d + 2];
            s3 += qr[d + 3] * ks[k][d + 3];
        }
        float s = ((s0 + s1) + (s2 + s3)) * 0.125f + pm[k];
        float mn = fmaxf(m, s);
        float corr = expf(m - mn);
        float e = expf(s - mn);
        lsum = lsum * corr + e;
#pragma unroll
        for (int d = 0; d < HD_; d++) acc[d] = acc[d] * corr + e * vs[k][d];
        m = mn;
    }
    float inv = 1.0f / lsum;
    float* orow = o + (size_t)(b * L_ + q) * D_ + h * HD_;
#pragma unroll
    for (int d = 0; d < HD_; d++) orow[d] = acc[d] * inv;
}

// ---------------- fused residual add + LayerNorm ----------------
__global__ __launch_bounds__(128) void add_ln_kernel(
                              float* __restrict__ x, const float* __restrict__ y, int ybatch,
                              const float* __restrict__ s, const float* __restrict__ b) {
    int n = blockIdx.x;
    float* xr = x + (size_t)n * D_;
    const float* yr = y + (size_t)(ybatch ? (n / L_) : n) * D_;
    int t = threadIdx.x;
    float4 xv = ((const float4*)xr)[t];
    float4 yv = ((const float4*)yr)[t];
    float v0 = xv.x + yv.x, v1 = xv.y + yv.y, v2 = xv.z + yv.z, v3 = xv.w + yv.w;
    float sum = v0 + v1 + v2 + v3;
    float sq  = v0 * v0 + v1 * v1 + v2 * v2 + v3 * v3;
#pragma unroll
    for (int off = 16; off > 0; off >>= 1) {
        sum += __shfl_xor_sync(0xffffffffu, sum, off);
        sq  += __shfl_xor_sync(0xffffffffu, sq,  off);
    }
    __shared__ float rs[4], rq[4];
    int wid = t >> 5, lane = t & 31;
    if (lane == 0) { rs[wid] = sum; rq[wid] = sq; }
    __syncthreads();
    sum = rs[0] + rs[1] + rs[2] + rs[3];
    sq  = rq[0] + rq[1] + rq[2] + rq[3];
    float mean = sum * (1.0f / D_);
    float var  = sq  * (1.0f / D_) - mean * mean;
    float rstd = rsqrtf(var + 1e-5f);
    float4 sv = ((const float4*)s)[t];
    float4 bv = ((const float4*)b)[t];
    float4 o;
    o.x = (v0 - mean) * rstd * sv.x + bv.x;
    o.y = (v1 - mean) * rstd * sv.y + bv.y;
    o.z = (v2 - mean) * rstd * sv.z + bv.z;
    o.w = (v3 - mean) * rstd * sv.w + bv.w;
    ((float4*)xr)[t] = o;
}

// ---------------- launch ----------------
static inline void launch_gemm(int Nrows, int M, int K, int lda,
                               const float* A, const float* W,
                               const float* bias, float* C, int relu) {
    dim3 g((M + 255) / 256, Nrows / 128);
    tgemm<<<g, 256, SM_BYTES>>>(M, K, lda, A, W, bias, C, relu);
}

extern "C" void kernel_launch(void* const* d_in, const int* in_sizes, int n_in,
                              void* d_out, int out_size) {
    const float* encoder_out = (const float*)d_in[0];
    const float* point_out   = (const float*)d_in[1];
    const float* emb         = (const float*)d_in[2];
    const float* pos_embed   = (const float*)d_in[3];
    const float* sa_inw      = (const float*)d_in[4];
    const float* sa_inb      = (const float*)d_in[5];
    const float* sa_outw     = (const float*)d_in[6];
    const float* sa_outb     = (const float*)d_in[7];
    const float* ca_inw      = (const float*)d_in[8];
    const float* ca_inb      = (const float*)d_in[9];
    const float* ca_outw     = (const float*)d_in[10];
    const float* ca_outb     = (const float*)d_in[11];
    const float* ln1_s       = (const float*)d_in[12];
    const float* ln1_b       = (const float*)d_in[13];
    const float* ln2_s       = (const float*)d_in[14];
    const float* ln2_b       = (const float*)d_in[15];
    const float* ln3_s       = (const float*)d_in[16];
    const float* ln3_b       = (const float*)d_in[17];
    const float* ff1_w       = (const float*)d_in[18];
    const float* ff1_b       = (const float*)d_in[19];
    const float* ff2_w       = (const float*)d_in[20];
    const float* ff2_b       = (const float*)d_in[21];
    const float* out_w       = (const float*)d_in[22];
    const float* out_b       = (const float*)d_in[23];
    const int*   tgt         = (const int*)d_in[24];

    cudaFuncSetAttribute(tgemm, cudaFuncAttributeMaxDynamicSharedMemorySize, SM_BYTES);

    float *x, *t, *qkv, *h, *vmem, *yca, *pm;
    cudaGetSymbolAddress((void**)&x,    g_x);
    cudaGetSymbolAddress((void**)&t,    g_t);
    cudaGetSymbolAddress((void**)&qkv,  g_qkv);
    cudaGetSymbolAddress((void**)&h,    g_h);
    cudaGetSymbolAddress((void**)&vmem, g_vmem);
    cudaGetSymbolAddress((void**)&yca,  g_yca);
    cudaGetSymbolAddress((void**)&pm,   g_padmask);

    embed_kernel<<<NTOK, 128>>>(emb, point_out, pos_embed, tgt, x, pm);

    for (int i = 0; i < NL_; i++) {
        const float* sa_w_i   = sa_inw  + (size_t)i * 3 * D_ * D_;
        const float* sa_b_i   = sa_inb  + (size_t)i * 3 * D_;
        const float* sa_ow_i  = sa_outw + (size_t)i * D_ * D_;
        const float* sa_ob_i  = sa_outb + (size_t)i * D_;
        const float* ca_wv_i  = ca_inw  + ((size_t)i * 3 * D_ + 2 * D_) * D_;  // V slice
        const float* ca_bv_i  = ca_inb  + (size_t)i * 3 * D_ + 2 * D_;
        const float* ca_ow_i  = ca_outw + (size_t)i * D_ * D_;
        const float* ca_ob_i  = ca_outb + (size_t)i * D_;
        const float* f1w_i    = ff1_w   + (size_t)i * DFF_ * D_;
        const float* f1b_i    = ff1_b   + (size_t)i * DFF_;
        const float* f2w_i    = ff2_w   + (size_t)i * D_ * DFF_;
        const float* f2b_i    = ff2_b   + (size_t)i * D_;

        // ---- self attention ----
        launch_gemm(NTOK, 3 * D_, D_, D_, x, sa_w_i, sa_b_i, qkv, 0);
        attn_kernel<<<B_ * NH_, 64>>>(qkv, pm, h);
        launch_gemm(NTOK, D_, D_, D_, h, sa_ow_i, sa_ob_i, t, 0);
        add_ln_kernel<<<NTOK, 128>>>(x, t, 0, ln1_s + i * D_, ln1_b + i * D_);

        // ---- cross attention (single memory token: output = V(mem) @ Wout + b,
        //      constant over query positions; Q/K provably irrelevant) ----
        launch_gemm(B_, D_, D_, SENC_ * D_, encoder_out, ca_wv_i, ca_bv_i, vmem, 0);
        launch_gemm(B_, D_, D_, D_, vmem, ca_ow_i, ca_ob_i, yca, 0);
        add_ln_kernel<<<NTOK, 128>>>(x, yca, 1, ln2_s + i * D_, ln2_b + i * D_);

        // ---- FFN ----
        launch_gemm(NTOK, DFF_, D_, D_, x, f1w_i, f1b_i, h, 1);
        launch_gemm(NTOK, D_, DFF_, DFF_, h, f2w_i, f2b_i, t, 0);
        add_ln_kernel<<<NTOK, 128>>>(x, t, 0, ln3_s + i * D_, ln3_b + i * D_);
    }

    // ---- final logits ----
    launch_gemm(NTOK, VOCAB, D_, D_, x, out_w, out_b, (float*)d_out, 0);
}